// round 12
// baseline (speedup 1.0000x reference)
#include <cuda_runtime.h>

// EKVNonLinearConv: w-space PWL table + per-(cout-pair,ci) sorted term lists with
// precomputed per-(ci,warp) iteration counts (counted loop, no data-dependent break).
//   f(d) = sp(min(a,20))^2 - sp(min(a-D,20))^2, a=d/0.075 ; out = ALPHA*R*scale*sum f
//   u = saturate(vg*INVR + ub), ub=(0.96-clip(th,1,8))/2.56 ; w = u*(1-2^-23)+1 in [1,2)
//   idx = top 9 mantissa bits of w ; 512 intervals, h_d = 0.005 ; kinks d=1.5 -> 492,
//   d=1.6 -> right edge of 511 (line hits 0 exactly). d<<0 -> entry 0 (~5e-12).

#define CIN    16
#define COUTT  64
#define HH     32
#define WW     32
#define BB     8
#define CG     2
#define NWARP  8
#define PR     2
#define NTHR   256
#define RPB    16             // NWARP*PR output rows per block
#define TILR   18             // +2 halo
#define LPC    144
#define NCG    32             // cout-pair groups

#define TABN   512
#define TD0    (-0.96f)
#define THD    0.005f                // 2.56/512
#define INVR   0.390625f             // 1/2.56 (exact dyadic)
#define SCL2   0.99999988f           // 1 - 2^-23: keeps w < 2.0 at u == 1
#define CUTC   0.41f                 // 0.96 - 0.55 (skip margin; f(-0.55) ~ 4e-7)

__device__ float2 g_tab[TABN];            // (a0,a1): f ~= a1*w + a0
__device__ float4 g_list[NCG * CIN * 9];  // {ub_c0, off_c0, ub_c1, off_c1} sorted desc

__device__ __forceinline__ float ekv_exact(float d) {
    const float INVD  = 13.333333333333334f;
    const float DELTA = 1.3333333333333333f;
    float a  = d * INVD;
    float a1 = fminf(fmaxf(a, -50.0f), 20.0f);
    float a2 = fminf(fmaxf(a - DELTA, -50.0f), 20.0f);
    float l1 = log1pf(expf(a1));
    float l2 = log1pf(expf(a2));
    return fmaf(l1, l1, -l2 * l2);
}

__global__ void prep_kernel(const float* __restrict__ theta) {
    int tid = threadIdx.x;
    if (blockIdx.x == NCG) {            // table builder block
        for (int i = tid; i < TABN; i += NTHR) {
            float f0 = ekv_exact(TD0 + (float)i * THD);
            float f1 = ekv_exact(TD0 + (float)(i + 1) * THD);
            float a1 = (f1 - f0) * 512.0f;            // slope per unit w
            float w0 = 1.0f + (float)i * (1.0f / 512.0f);
            g_tab[i] = make_float2(fmaf(-a1, w0, f0), a1);
        }
        return;
    }
    int cg = blockIdx.x;
    if (tid < CIN) {
        int ci = tid;
        float ub[CG][9]; int off[CG][9];
        #pragma unroll
        for (int c = 0; c < CG; c++) {
            const float* tp = theta + (cg * CG + c) * LPC + ci * 9;
            #pragma unroll
            for (int e = 0; e < 9; e++) {
                float th = fminf(fmaxf(tp[e], 1.0f), 8.0f);
                ub[c][e] = (0.96f - th) * INVR;
                int ky = e / 3, kx = e - ky * 3;
                off[c][e] = (ky * 34 + kx) * 4;   // byte offset in tile slab
            }
            // selection sort, descending (deterministic)
            for (int i = 0; i < 8; i++) {
                int m = i;
                for (int j = i + 1; j < 9; j++) if (ub[c][j] > ub[c][m]) m = j;
                float tu = ub[c][i]; ub[c][i] = ub[c][m]; ub[c][m] = tu;
                int   to = off[c][i]; off[c][i] = off[c][m]; off[c][m] = to;
            }
        }
        float4* dst = g_list + (cg * CIN + ci) * 9;
        for (int e = 0; e < 9; e++)
            dst[e] = make_float4(ub[0][e], __int_as_float(off[0][e]),
                                 ub[1][e], __int_as_float(off[1][e]));
    }
}

__global__ __launch_bounds__(NTHR)
void ekv_conv_kernel(const float* __restrict__ x,
                     const float* __restrict__ scale,
                     float* __restrict__ out)
{
    __shared__ float  sx[CIN][TILR][34];   // 38.25 KB halo tile
    __shared__ float4 slist[CIN * 9];      // 2.25 KB fused sorted lists
    __shared__ float2 tab[TABN];           // 4 KB
    __shared__ float  srm[CIN][TILR];      // per-(ci,row) max
    __shared__ int    scnt[CIN][NWARP];    // per-(ci,warp) iteration count

    const int rt = blockIdx.x;       // 0..1
    const int cg = blockIdx.y;       // 0..31
    const int b  = blockIdx.z;
    const int y0 = rt * RPB;
    const int tid = threadIdx.x;

    for (int i = tid; i < TABN; i += NTHR) tab[i] = g_tab[i];
    {
        const float4* src = g_list + cg * (CIN * 9);
        for (int i = tid; i < CIN * 9; i += NTHR) slist[i] = src[i];
    }
    for (int i = tid; i < CIN * TILR * 34; i += NTHR) {
        int cc = i % 34;
        int r  = (i / 34) % TILR;
        int ci = i / (34 * TILR);
        int gy = y0 - 1 + r;
        int gx = cc - 1;
        float v = 0.0f;
        if (gy >= 0 && gy < HH && gx >= 0 && gx < WW)
            v = x[((b * CIN + ci) * HH + gy) * WW + gx];
        sx[ci][r][cc] = v;
    }
    __syncthreads();
    for (int i = tid; i < CIN * TILR; i += NTHR) {
        int r  = i % TILR;
        int ci = i / TILR;
        float m = -1e30f;
        #pragma unroll
        for (int cc = 0; cc < 34; cc++) m = fmaxf(m, sx[ci][r][cc]);
        srm[ci][r] = m;
    }
    __syncthreads();
    if (tid < CIN * NWARP) {   // one thread per (ci, warp): count active entry-pairs
        int w = tid & 7, ci = tid >> 3;
        float m = fmaxf(fmaxf(srm[ci][2 * w], srm[ci][2 * w + 1]),
                        fmaxf(srm[ci][2 * w + 2], srm[ci][2 * w + 3]));
        float cut = (CUTC - m) * INVR;
        const float4* l = &slist[ci * 9];
        int n = 0;
        #pragma unroll
        for (int e = 0; e < 9; e++)
            if (fmaxf(l[e].x, l[e].z) > cut) n++;   // monotone -> prefix length
        scnt[ci][w] = n;
    }
    __syncthreads();

    const int tx  = tid & 31;
    const int wid = tid >> 5;

    float accA0 = 0.0f, accB0 = 0.0f;   // cout c0,   pixel rows A/B
    float accA1 = 0.0f, accB1 = 0.0f;   // cout c0+1

#define EKV_PIX(VG, UB, ACC) do {                                    \
        float u_ = __saturatef(fmaf((VG), INVR, (UB)));              \
        float w_ = fmaf(u_, SCL2, 1.0f);                             \
        int o_ = (__float_as_int(w_) >> 11) & 0xFF8;                 \
        float2 e_ = *(const float2*)((const char*)tab + o_);         \
        (ACC) += fmaf(e_.y, w_, e_.x);                               \
    } while (0)

    #pragma unroll 1
    for (int ci = 0; ci < CIN; ci++) {
        const int n = scnt[ci][wid];                       // warp-uniform
        const char* base = (const char*)&sx[ci][wid * PR][tx];
        const float4* l = &slist[ci * 9];
        #pragma unroll 1
        for (int e = 0; e < n; e++) {
            float4 pe = l[e];                              // 1 LDS.128, broadcast
            const float* p0 = (const float*)(base + __float_as_int(pe.y));
            const float* p1 = (const float*)(base + __float_as_int(pe.w));
            float vA0 = p0[0], vB0 = p0[34];
            float vA1 = p1[0], vB1 = p1[34];
            EKV_PIX(vA0, pe.x, accA0);                     // 4 independent chains
            EKV_PIX(vB0, pe.x, accB0);
            EKV_PIX(vA1, pe.z, accA1);
            EKV_PIX(vB1, pe.z, accB1);
        }
    }
#undef EKV_PIX

    const float sc = scale[0] * (0.05625f * 0.1f);   // ALPHA * R * scale
    const int yA = y0 + wid * PR;
    const int co = cg * CG;
    out[((b * COUTT + co + 0) * HH + yA + 0) * WW + tx] = accA0 * sc;
    out[((b * COUTT + co + 0) * HH + yA + 1) * WW + tx] = accB0 * sc;
    out[((b * COUTT + co + 1) * HH + yA + 0) * WW + tx] = accA1 * sc;
    out[((b * COUTT + co + 1) * HH + yA + 1) * WW + tx] = accB1 * sc;
}

extern "C" void kernel_launch(void* const* d_in, const int* in_sizes, int n_in,
                              void* d_out, int out_size) {
    const float* x     = (const float*)d_in[0];
    const float* theta = (const float*)d_in[1];
    const float* scale = (const float*)d_in[2];
    float* out = (float*)d_out;
    (void)in_sizes; (void)n_in; (void)out_size;

    prep_kernel<<<NCG + 1, NTHR>>>(theta);

    dim3 grid(HH / RPB, NCG, BB);   // 2 x 32 x 8 = 512 blocks
    dim3 block(NTHR);
    ekv_conv_kernel<<<grid, block>>>(x, scale, out);
}